// round 15
// baseline (speedup 1.0000x reference)
#include <cuda_runtime.h>
#include <cuda_bf16.h>
#include <math.h>

#define BB 512
#define TT 256
#define EE 256
#define UU 512
#define G4 2048   // 4*U
#define VV 10000
#define HH 64

#define ASTR 24       // A smem row stride in bf16 elems (48B, conflict-free ldmatrix)
#define NCTA 128      // persistent scan grid
#define GRPSZ 16      // CTAs per barrier group (one (dir, m-tile) pipeline)

// dynamic smem layout for k_scanp (bytes)
#define SM_BH 0                        // Wh-hi persistent: 512*128*2 = 131072
#define SM_AH 131072                   // A-hi stages: 2*128*ASTR*2 = 12288
#define SM_AL (131072 + 12288)         // A-lo stages: 12288
#define SM_BL (131072 + 24576)         // Wh-lo stages: 2*16*128*2 = 8192
#define SM_XW (131072 + 24576 + 8192)  // xw tile: 128*128*4 = 65536
#define SMEM_TOT (SM_XW + 65536)       // 229376 (<= 232448 cap)

// ---- scratch (static device memory) ----
__device__ float g_xw[2ull * BB * TT * G4];   // x@Wx, layout (dir, time, b, j) fp32
__device__ float g_h[2 * BB * UU];            // final-step h (fp32, for MLP tail)
__device__ __nv_bfloat16 g_hh[2][2 * BB * UU];  // h hi, double-buffered by step parity
__device__ __nv_bfloat16 g_hl[2][2 * BB * UU];  // h lo
__device__ float g_hidden[BB * HH];
__device__ __nv_bfloat16 g_wxh[2 * EE * G4], g_wxl[2 * EE * G4];  // Wx interleaved+split
__device__ __nv_bfloat16 g_whh[2 * UU * G4], g_whl[2 * UU * G4];  // Wh interleaved+split
__device__ float g_b[2 * G4];                                      // bias interleaved
__device__ __nv_bfloat16 g_eh[(size_t)VV * EE], g_el[(size_t)VV * EE]; // emb split
__device__ unsigned g_bcnt[8];
__device__ unsigned g_bgen[8];

__device__ __forceinline__ float sigf(float x) { return 1.0f / (1.0f + expf(-x)); }

__device__ __forceinline__ unsigned sptr(const void* p) {
    return (unsigned)__cvta_generic_to_shared(p);
}
__device__ __forceinline__ void ldsm4(unsigned r[4], unsigned addr) {
    asm volatile("ldmatrix.sync.aligned.m8n8.x4.shared.b16 {%0,%1,%2,%3}, [%4];"
                 : "=r"(r[0]), "=r"(r[1]), "=r"(r[2]), "=r"(r[3]) : "r"(addr));
}
__device__ __forceinline__ void ldsm4t(unsigned r[4], unsigned addr) {
    asm volatile("ldmatrix.sync.aligned.m8n8.x4.trans.shared.b16 {%0,%1,%2,%3}, [%4];"
                 : "=r"(r[0]), "=r"(r[1]), "=r"(r[2]), "=r"(r[3]) : "r"(addr));
}
__device__ __forceinline__ void mma_bf16(float c[4], const unsigned a[4], const unsigned* b) {
    asm volatile(
        "mma.sync.aligned.m16n8k16.row.col.f32.bf16.bf16.f32 "
        "{%0,%1,%2,%3}, {%4,%5,%6,%7}, {%8,%9}, {%0,%1,%2,%3};"
        : "+f"(c[0]), "+f"(c[1]), "+f"(c[2]), "+f"(c[3])
        : "r"(a[0]), "r"(a[1]), "r"(a[2]), "r"(a[3]), "r"(b[0]), "r"(b[1]));
}
__device__ __forceinline__ void cpasync16(unsigned saddr, const void* gaddr) {
    asm volatile("cp.async.cg.shared.global [%0], [%1], 16;"
                 :: "r"(saddr), "l"(gaddr) : "memory");
}

// ---------------------------------------------------------------
__global__ void k_zero() {
    int i = blockIdx.x * blockDim.x + threadIdx.x;
    if (i < 8) { g_bcnt[i] = 0; g_bgen[i] = 0; }
    if (i < 2 * BB * UU) {
        __nv_bfloat16 z = __float2bfloat16(0.0f);
        g_hh[0][i] = z; g_hl[0][i] = z;
    }
}

// ---------------------------------------------------------------
// One-shot prep: gate-interleave (j = 4u+g) + bf16 hi/lo split of all
// GEMM operands (Wx, Wh, emb); bias interleaved fp32.
// ---------------------------------------------------------------
__global__ void k_prep(const float* __restrict__ WxF, const float* __restrict__ WhF,
                       const float* __restrict__ bF,  const float* __restrict__ WxB,
                       const float* __restrict__ WhB, const float* __restrict__ bB,
                       const float* __restrict__ emb) {
    const int PER = (EE + UU + 1) * G4;
    const int W_TOT = 2 * PER;
    const size_t E_TOT = (size_t)VV * EE;
    size_t tid = (size_t)blockIdx.x * 256 + threadIdx.x;
    if (tid < (size_t)W_TOT) {
        int dir = (int)(tid / PER);
        int r = (int)(tid % PER);
        int row = r / G4, j = r % G4;
        int oc = (j & 3) * UU + (j >> 2);
        float v;
        if (row < EE)            v = (dir ? WxB : WxF)[(size_t)row * G4 + oc];
        else if (row < EE + UU)  v = (dir ? WhB : WhF)[(size_t)(row - EE) * G4 + oc];
        else                     v = (dir ? bB : bF)[oc];
        __nv_bfloat16 h = __float2bfloat16(v);
        __nv_bfloat16 l = __float2bfloat16(v - __bfloat162float(h));
        if (row < EE) {
            size_t o = (size_t)dir * EE * G4 + (size_t)row * G4 + j;
            g_wxh[o] = h; g_wxl[o] = l;
        } else if (row < EE + UU) {
            size_t o = (size_t)dir * UU * G4 + (size_t)(row - EE) * G4 + j;
            g_whh[o] = h; g_whl[o] = l;
        } else {
            g_b[dir * G4 + j] = v;
        }
    } else if (tid < (size_t)W_TOT + E_TOT) {
        size_t i = tid - W_TOT;
        float v = emb[i];
        __nv_bfloat16 h = __float2bfloat16(v);
        g_eh[i] = h;
        g_el[i] = __float2bfloat16(v - __bfloat162float(h));
    }
}

// ---------------------------------------------------------------
// Precompute XW = gather(emb_split, sent) @ Wx_split. Output layout
// (dir, time, b, j). M-tile = 128 batch rows at ONE time step.
// Tile 128x128, KC=16, 256 thr, warps 2m x 4n (warp tile 64x32).
// ---------------------------------------------------------------
__global__ __launch_bounds__(256) void k_pre(const int* __restrict__ sent) {
    const int dir = blockIdx.z;
    const __nv_bfloat16* __restrict__ Bh_g = g_wxh + (size_t)dir * EE * G4;
    const __nv_bfloat16* __restrict__ Bl_g = g_wxl + (size_t)dir * EE * G4;
    const int n0 = blockIdx.x * 128;
    const int time = blockIdx.y % TT;
    const int mb = (blockIdx.y / TT) * 128;

    __shared__ __nv_bfloat16 Ah_s[2][128 * ASTR], Al_s[2][128 * ASTR];
    __shared__ __nv_bfloat16 Bh_s[2][16 * 128], Bl_s[2][16 * 128];
    __shared__ int tok[128];

    const int tid = threadIdx.x;
    const int lane = tid & 31, w = tid >> 5;
    const int wm = w >> 2, wn = w & 3;
    const int gi = lane >> 2, ct = lane & 3;

    if (tid < 128) tok[tid] = sent[(size_t)(mb + tid) * TT + time];
    __syncthreads();

    const int arow = tid >> 1, ahalf = tid & 1;
    const int bk = tid >> 4, bc = tid & 15;
    const size_t tokA = (size_t)tok[arow];
    const int bsw = ((bc * 8) ^ ((bk & 7) << 3));

    const __nv_bfloat16* pa_h = g_eh + tokA * EE + ahalf * 8;
    const __nv_bfloat16* pa_l = g_el + tokA * EE + ahalf * 8;
    const __nv_bfloat16* pb_h = Bh_g + (size_t)bk * G4 + n0 + bc * 8;
    const __nv_bfloat16* pb_l = Bl_g + (size_t)bk * G4 + n0 + bc * 8;

    float acc[4][4][4];
#pragma unroll
    for (int i = 0; i < 4; i++)
#pragma unroll
        for (int j = 0; j < 4; j++)
#pragma unroll
            for (int q = 0; q < 4; q++) acc[i][j][q] = 0.0f;

    {
        uint4 vah = *(const uint4*)pa_h;
        uint4 val = *(const uint4*)pa_l;
        uint4 vbh = *(const uint4*)pb_h;
        uint4 vbl = *(const uint4*)pb_l;
        *(uint4*)&Ah_s[0][arow * ASTR + ahalf * 8] = vah;
        *(uint4*)&Al_s[0][arow * ASTR + ahalf * 8] = val;
        *(uint4*)&Bh_s[0][bk * 128 + bsw] = vbh;
        *(uint4*)&Bl_s[0][bk * 128 + bsw] = vbl;
    }
    __syncthreads();

    const int NK = EE / 16;
    int cur = 0;
    for (int kk = 1; kk <= NK; kk++) {
        uint4 vah, val, vbh, vbl;
        if (kk < NK) {
            vah = *(const uint4*)(pa_h + kk * 16);
            val = *(const uint4*)(pa_l + kk * 16);
            vbh = *(const uint4*)(pb_h + (size_t)kk * 16 * G4);
            vbl = *(const uint4*)(pb_l + (size_t)kk * 16 * G4);
        }
        unsigned afh[4][4], afl[4][4], bfh[2][4], bfl[2][4];
        {
            unsigned abh = sptr(Ah_s[cur]), abl = sptr(Al_s[cur]);
            unsigned aoff = ((wm * 64 + (lane & 15)) * ASTR + (lane >> 4) * 8) * 2;
#pragma unroll
            for (int mt = 0; mt < 4; mt++) {
                ldsm4(afh[mt], abh + aoff + mt * 16 * ASTR * 2);
                ldsm4(afl[mt], abl + aoff + mt * 16 * ASTR * 2);
            }
            unsigned bbh = sptr(Bh_s[cur]), bbl = sptr(Bl_s[cur]);
            int k = lane & 15;
#pragma unroll
            for (int nh = 0; nh < 2; nh++) {
                unsigned nb = (unsigned)((wn * 32 + nh * 16) * 2 + (lane >> 4) * 16);
                unsigned ba = k * 256 + (nb ^ ((k & 7) << 4));
                ldsm4t(bfh[nh], bbh + ba);
                ldsm4t(bfl[nh], bbl + ba);
            }
        }
#pragma unroll
        for (int mt = 0; mt < 4; mt++)
#pragma unroll
            for (int nh = 0; nh < 2; nh++)
#pragma unroll
                for (int sub = 0; sub < 2; sub++) {
                    float* a = acc[mt][nh * 2 + sub];
                    mma_bf16(a, afh[mt], bfh[nh] + sub * 2);
                    mma_bf16(a, afh[mt], bfl[nh] + sub * 2);
                    mma_bf16(a, afl[mt], bfh[nh] + sub * 2);
                }
        if (kk < NK) {
            int nx = cur ^ 1;
            *(uint4*)&Ah_s[nx][arow * ASTR + ahalf * 8] = vah;
            *(uint4*)&Al_s[nx][arow * ASTR + ahalf * 8] = val;
            *(uint4*)&Bh_s[nx][bk * 128 + bsw] = vbh;
            *(uint4*)&Bl_s[nx][bk * 128 + bsw] = vbl;
            __syncthreads();
        }
        cur ^= 1;
    }

    // write (dir, time, b, j)
    float* out = g_xw + ((size_t)(dir * TT + time) * BB) * G4;
#pragma unroll
    for (int mt = 0; mt < 4; mt++) {
#pragma unroll
        for (int nt = 0; nt < 4; nt++) {
            size_t r0 = (size_t)mb + wm * 64 + mt * 16 + gi;
            int cl = n0 + wn * 32 + nt * 8 + 2 * ct;
            *(float2*)(out + r0 * G4 + cl) = make_float2(acc[mt][nt][0], acc[mt][nt][1]);
            *(float2*)(out + (r0 + 8) * G4 + cl) = make_float2(acc[mt][nt][2], acc[mt][nt][3]);
        }
    }
}

// ---------------------------------------------------------------
// Persistent scan: one launch, 256 steps. 128 CTAs = 8 independent
// groups of 16; per-group grid barrier. 512 threads (16 warps, 4m x 4n,
// 32x32 warp tiles) for latency hiding. Wh-hi persistent in smem;
// Wh-lo + h hi/lo streamed; xw prefetched via cp.async; c in registers.
// ---------------------------------------------------------------
__global__ __launch_bounds__(512) void k_scanp() {
    extern __shared__ __align__(16) char smem[];
    __nv_bfloat16* Bh_p = (__nv_bfloat16*)(smem + SM_BH);   // [512][128] swizzled
    __nv_bfloat16* Ah_s = (__nv_bfloat16*)(smem + SM_AH);   // [2][128*ASTR]
    __nv_bfloat16* Al_s = (__nv_bfloat16*)(smem + SM_AL);
    __nv_bfloat16* Bl_s = (__nv_bfloat16*)(smem + SM_BL);   // [2][16*128] swizzled
    float*         xw_s = (float*)(smem + SM_XW);           // [128][128]

    const int tid = threadIdx.x;
    const int lane = tid & 31, w = tid >> 5;
    const int wm = w & 3, wn = w >> 2;      // 4m x 4n warps, 32x32 tiles
    const int gi = lane >> 2, ct = lane & 3;
    const int bid = blockIdx.x;
    const int dir = bid >> 6;
    const int m0 = ((bid >> 4) & 3) * 128;
    const int n0 = (bid & 15) * 128;
    const int grp = bid >> 4;   // 8 groups of 16 CTAs

    // staging roles: tid<256 -> A-hi + Wh-lo; tid>=256 -> A-lo
    const int at = tid & 255;
    const int arow = at >> 1, ahalf = at & 1;
    const int bk = at >> 4, bc = at & 15;
    const int bsw = ((bc * 8) ^ ((bk & 7) << 3));
    const bool loadHi = (tid < 256);

    const __nv_bfloat16* __restrict__ Bh_g = g_whh + (size_t)dir * UU * G4 + n0;
    const __nv_bfloat16* __restrict__ Bl_g = g_whl + (size_t)dir * UU * G4 + n0;
    const float* __restrict__ bias = g_b + dir * G4;

    // persistent Wh-hi preload (swizzled for ldmatrix-trans)
    for (int it = 0; it < 16; it++) {
        int idx = tid + it * 512;
        int row = idx >> 4, c8 = idx & 15;
        uint4 v = *(const uint4*)(Bh_g + (size_t)row * G4 + c8 * 8);
        unsigned eoff = (unsigned)(row * 128 + ((c8 * 8) ^ ((row & 7) << 3)));
        *(uint4*)(Bh_p + eoff) = v;
    }

    float creg[2][4][2];
#pragma unroll
    for (int i = 0; i < 2; i++)
#pragma unroll
        for (int j = 0; j < 4; j++) { creg[i][j][0] = 0.0f; creg[i][j][1] = 0.0f; }

    __syncthreads();

    const size_t hoffA = (size_t)dir * BB * UU + (size_t)(m0 + arow) * UU + ahalf * 8;
    const size_t hb = (size_t)dir * BB * UU;
    const unsigned xw_sb = sptr(xw_s);

    for (int t = 0; t < TT; t++) {
        const int rp = t & 1, wp = rp ^ 1;
        const int time = dir ? (TT - 1 - t) : t;
        // staging source: hi for lower half of threads, lo for upper half
        const __nv_bfloat16* pa = (loadHi ? g_hh[rp] : g_hl[rp]) + hoffA;

        // xw prefetch (coalesced; hidden behind the k-loop)
        {
            const float* xw_src =
                g_xw + ((size_t)(dir * TT + time) * BB + m0) * G4 + n0;
#pragma unroll
            for (int it = 0; it < 8; it++) {
                int idx = tid + it * 512;
                int row = idx >> 5, c4 = (idx & 31) * 4;
                cpasync16(xw_sb + (unsigned)(row * 128 + c4) * 4,
                          xw_src + (size_t)row * G4 + c4);
            }
            asm volatile("cp.async.commit_group;" ::: "memory");
        }

        // stage k-chunk 0
        {
            uint4 va = *(const uint4*)pa;
            if (loadHi) {
                uint4 vbl = *(const uint4*)(Bl_g + (size_t)bk * G4 + bc * 8);
                *(uint4*)&Ah_s[arow * ASTR + ahalf * 8] = va;
                *(uint4*)&Bl_s[bk * 128 + bsw] = vbl;
            } else {
                *(uint4*)&Al_s[arow * ASTR + ahalf * 8] = va;
            }
        }
        __syncthreads();

        float acc[2][4][4];
#pragma unroll
        for (int i = 0; i < 2; i++)
#pragma unroll
            for (int j = 0; j < 4; j++)
#pragma unroll
                for (int q = 0; q < 4; q++) acc[i][j][q] = 0.0f;

        const int NK = UU / 16;  // 32
        int cur = 0;
        for (int kk = 1; kk <= NK; kk++) {
            uint4 va, vbl;
            if (kk < NK) {
                va = *(const uint4*)(pa + kk * 16);
                if (loadHi)
                    vbl = *(const uint4*)(Bl_g + (size_t)(kk * 16 + bk) * G4 + bc * 8);
            }
            unsigned afh[2][4], afl[2][4], bfh[2][4], bfl[2][4];
            {
                unsigned abh = sptr(Ah_s) + cur * (128 * ASTR * 2);
                unsigned abl = sptr(Al_s) + cur * (128 * ASTR * 2);
                unsigned aoff = ((wm * 32 + (lane & 15)) * ASTR + (lane >> 4) * 8) * 2;
#pragma unroll
                for (int mt = 0; mt < 2; mt++) {
                    ldsm4(afh[mt], abh + aoff + mt * 16 * ASTR * 2);
                    ldsm4(afl[mt], abl + aoff + mt * 16 * ASTR * 2);
                }
                int k = lane & 15;
                int kr = (kk - 1) * 16 + k;
                unsigned bbl = sptr(Bl_s) + cur * 4096;
#pragma unroll
                for (int nh = 0; nh < 2; nh++) {
                    unsigned nb = (unsigned)((wn * 32 + nh * 16) * 2 + (lane >> 4) * 16);
                    ldsm4t(bfh[nh], sptr(Bh_p) + kr * 256 + (nb ^ ((kr & 7) << 4)));
                    ldsm4t(bfl[nh], bbl + k * 256 + (nb ^ ((k & 7) << 4)));
                }
            }
#pragma unroll
            for (int mt = 0; mt < 2; mt++)
#pragma unroll
                for (int nh = 0; nh < 2; nh++)
#pragma unroll
                    for (int sub = 0; sub < 2; sub++) {
                        float* a = acc[mt][nh * 2 + sub];
                        mma_bf16(a, afh[mt], bfh[nh] + sub * 2);
                        mma_bf16(a, afh[mt], bfl[nh] + sub * 2);
                        mma_bf16(a, afl[mt], bfh[nh] + sub * 2);
                    }
            if (kk < NK) {
                int nx = cur ^ 1;
                if (loadHi) {
                    *(uint4*)&Ah_s[nx * (128 * ASTR) + arow * ASTR + ahalf * 8] = va;
                    *(uint4*)&Bl_s[nx * 2048 + bk * 128 + bsw] = vbl;
                } else {
                    *(uint4*)&Al_s[nx * (128 * ASTR) + arow * ASTR + ahalf * 8] = va;
                }
                __syncthreads();
            }
            cur ^= 1;
        }

        // make xw tile visible to all threads
        asm volatile("cp.async.wait_group 0;" ::: "memory");
        __syncthreads();

        // epilogue: + xw + bias, shfl-pair (i,f)<->(g,o), LSTM cell (c in regs),
        // write h hi/lo to parity buffer; fp32 h only on last step.
#pragma unroll
        for (int mt = 0; mt < 2; mt++) {
#pragma unroll
            for (int nt = 0; nt < 4; nt++) {
                int lr0 = wm * 32 + mt * 16 + gi;
                int lcl = wn * 32 + nt * 8 + 2 * ct;
                int r0 = m0 + lr0, r1 = r0 + 8;
                int cl = n0 + lcl;
                float2 x0 = *(const float2*)&xw_s[lr0 * 128 + lcl];
                float2 x1 = *(const float2*)&xw_s[(lr0 + 8) * 128 + lcl];
                float2 bb = *(const float2*)(bias + cl);
                float p00 = acc[mt][nt][0] + x0.x + bb.x;
                float p01 = acc[mt][nt][1] + x0.y + bb.y;
                float p10 = acc[mt][nt][2] + x1.x + bb.x;
                float p11 = acc[mt][nt][3] + x1.y + bb.y;
                float q00 = __shfl_xor_sync(0xFFFFFFFFu, p00, 1);
                float q01 = __shfl_xor_sync(0xFFFFFFFFu, p01, 1);
                float q10 = __shfl_xor_sync(0xFFFFFFFFu, p10, 1);
                float q11 = __shfl_xor_sync(0xFFFFFFFFu, p11, 1);
                if ((ct & 1) == 0) {
                    int u = cl >> 2;
                    size_t i0 = hb + (size_t)r0 * UU + u;
                    size_t i1 = hb + (size_t)r1 * UU + u;
                    float c0 = sigf(p01) * creg[mt][nt][0] + sigf(p00) * tanhf(q00);
                    float h0 = sigf(q01) * tanhf(c0);
                    creg[mt][nt][0] = c0;
                    __nv_bfloat16 h0h = __float2bfloat16(h0);
                    g_hh[wp][i0] = h0h;
                    g_hl[wp][i0] = __float2bfloat16(h0 - __bfloat162float(h0h));
                    float c1 = sigf(p11) * creg[mt][nt][1] + sigf(p10) * tanhf(q10);
                    float h1 = sigf(q11) * tanhf(c1);
                    creg[mt][nt][1] = c1;
                    __nv_bfloat16 h1h = __float2bfloat16(h1);
                    g_hh[wp][i1] = h1h;
                    g_hl[wp][i1] = __float2bfloat16(h1 - __bfloat162float(h1h));
                    if (t == TT - 1) { g_h[i0] = h0; g_h[i1] = h1; }
                }
            }
        }

        // per-group barrier (16 CTAs sharing (dir, m-tile)); skip after last step
        if (t + 1 < TT) {
            __threadfence();
            __syncthreads();
            if (tid == 0) {
                unsigned target = (unsigned)(t + 1);
                unsigned old = atomicAdd(&g_bcnt[grp], 1);
                if (old == GRPSZ - 1) {
                    atomicExch(&g_bcnt[grp], 0);
                    __threadfence();
                    atomicExch(&g_bgen[grp], target);
                } else {
                    unsigned g;
                    do {
                        asm volatile("ld.acquire.gpu.u32 %0, [%1];"
                                     : "=r"(g) : "l"(&g_bgen[grp]) : "memory");
                    } while (g < target);
                }
            }
            __syncthreads();
        }
    }
}

// ---------------------------------------------------------------
__global__ void k_hidden(const float* __restrict__ W1, const float* __restrict__ b1) {
    int b = blockIdx.x;
    int j = threadIdx.x;  // 64
    __shared__ float hrow[2 * UU];
    for (int k = j; k < UU; k += HH) {
        hrow[k] = g_h[(size_t)b * UU + k];
        hrow[UU + k] = g_h[(size_t)BB * UU + (size_t)b * UU + k];
    }
    __syncthreads();
    float s = b1[j];
    for (int k = 0; k < 2 * UU; k++) s = fmaf(hrow[k], W1[(size_t)k * HH + j], s);
    g_hidden[b * HH + j] = fmaxf(s, 0.0f);
}

// ---------------------------------------------------------------
__global__ void k_out(const float* __restrict__ W2, const float* __restrict__ b2,
                      float* __restrict__ out) {
    int b = blockIdx.x;
    int tid = threadIdx.x;
    __shared__ float hid[HH];
    __shared__ float red[256];
    if (tid < HH) hid[tid] = g_hidden[b * HH + tid];
    __syncthreads();

    float lmax = -3.0e38f;
    for (int v = tid; v < VV; v += 256) {
        float s = b2[v];
#pragma unroll
        for (int k = 0; k < HH; k++) s = fmaf(hid[k], W2[(size_t)k * VV + v], s);
        out[(size_t)b * VV + v] = s;
        lmax = fmaxf(lmax, s);
    }
    red[tid] = lmax;
    __syncthreads();
    for (int s = 128; s > 0; s >>= 1) {
        if (tid < s) red[tid] = fmaxf(red[tid], red[tid + s]);
        __syncthreads();
    }
    float mx = red[0];
    __syncthreads();

    float lsum = 0.0f;
    for (int v = tid; v < VV; v += 256) {
        float e = expf(out[(size_t)b * VV + v] - mx);
        out[(size_t)b * VV + v] = e;
        lsum += e;
    }
    red[tid] = lsum;
    __syncthreads();
    for (int s = 128; s > 0; s >>= 1) {
        if (tid < s) red[tid] += red[tid + s];
        __syncthreads();
    }
    float inv = 1.0f / red[0];
    __syncthreads();

    for (int v = tid; v < VV; v += 256) out[(size_t)b * VV + v] *= inv;
}

// ---------------------------------------------------------------
extern "C" void kernel_launch(void* const* d_in, const int* in_sizes, int n_in,
                              void* d_out, int out_size) {
    const int*   sent = (const int*)d_in[0];
    const float* emb  = (const float*)d_in[1];
    const float* WxF  = (const float*)d_in[2];
    const float* WhF  = (const float*)d_in[3];
    const float* bF   = (const float*)d_in[4];
    const float* WxB  = (const float*)d_in[5];
    const float* WhB  = (const float*)d_in[6];
    const float* bB   = (const float*)d_in[7];
    const float* W1   = (const float*)d_in[8];
    const float* b1   = (const float*)d_in[9];
    const float* W2   = (const float*)d_in[10];
    const float* b2   = (const float*)d_in[11];
    float* out = (float*)d_out;

    cudaFuncSetAttribute(k_scanp, cudaFuncAttributeMaxDynamicSharedMemorySize, SMEM_TOT);

    k_zero<<<(2 * BB * UU + 255) / 256, 256>>>();

    const size_t prep_total = (size_t)2 * (EE + UU + 1) * G4 + (size_t)VV * EE;
    k_prep<<<(int)((prep_total + 255) / 256), 256>>>(WxF, WhF, bF, WxB, WhB, bB, emb);

    dim3 gp(G4 / 128, (BB / 128) * TT, 2);  // (16, 1024, 2)
    k_pre<<<gp, 256>>>(sent);

    k_scanp<<<NCTA, 512, SMEM_TOT>>>();

    k_hidden<<<BB, HH>>>(W1, b1);
    k_out<<<BB, 256>>>(W2, b2, out);
}

// round 16
// speedup vs baseline: 1.0037x; 1.0037x over previous
#include <cuda_runtime.h>
#include <cuda_bf16.h>
#include <math.h>

#define BB 512
#define TT 256
#define EE 256
#define UU 512
#define G4 2048   // 4*U
#define VV 10000
#define HH 64

#define ASTR 24       // A smem row stride in bf16 elems (48B, conflict-free ldmatrix)
#define NCTA 128      // persistent scan grid
#define GRPSZ 16      // CTAs per barrier group (one (dir, m-tile) pipeline)

// dynamic smem layout for k_scanp (bytes)
#define SM_BH 0                        // Wh-hi persistent: 512*128*2 = 131072
#define SM_AH 131072                   // A-hi stages: 2*128*ASTR*2 = 12288
#define SM_AL (131072 + 12288)         // A-lo stages: 12288
#define SM_BL (131072 + 24576)         // Wh-lo stages: 2*16*128*2 = 8192
#define SM_XW (131072 + 24576 + 8192)  // xw tile: 128*128*4 = 65536
#define SMEM_TOT (SM_XW + 65536)       // 229376 (<= 232448 cap)

// ---- scratch (static device memory) ----
__device__ float g_xw[2ull * BB * TT * G4];   // x@Wx, layout (dir, time, b, j) fp32
__device__ float g_h[2 * BB * UU];            // final-step h (fp32, for MLP tail)
__device__ __nv_bfloat16 g_hh[2][2 * BB * UU];  // h hi, double-buffered by step parity
__device__ __nv_bfloat16 g_hl[2][2 * BB * UU];  // h lo
__device__ float g_hidden[BB * HH];
__device__ __nv_bfloat16 g_wxh[2 * EE * G4], g_wxl[2 * EE * G4];  // Wx interleaved+split
__device__ __nv_bfloat16 g_whh[2 * UU * G4], g_whl[2 * UU * G4];  // Wh interleaved+split
__device__ float g_b[2 * G4];                                      // bias interleaved
__device__ __nv_bfloat16 g_eh[(size_t)VV * EE], g_el[(size_t)VV * EE]; // emb split
__device__ unsigned g_bcnt[8];
__device__ unsigned g_bgen[8];

__device__ __forceinline__ float sigf(float x) { return 1.0f / (1.0f + expf(-x)); }

__device__ __forceinline__ unsigned sptr(const void* p) {
    return (unsigned)__cvta_generic_to_shared(p);
}
__device__ __forceinline__ void ldsm4(unsigned r[4], unsigned addr) {
    asm volatile("ldmatrix.sync.aligned.m8n8.x4.shared.b16 {%0,%1,%2,%3}, [%4];"
                 : "=r"(r[0]), "=r"(r[1]), "=r"(r[2]), "=r"(r[3]) : "r"(addr));
}
__device__ __forceinline__ void ldsm4t(unsigned r[4], unsigned addr) {
    asm volatile("ldmatrix.sync.aligned.m8n8.x4.trans.shared.b16 {%0,%1,%2,%3}, [%4];"
                 : "=r"(r[0]), "=r"(r[1]), "=r"(r[2]), "=r"(r[3]) : "r"(addr));
}
__device__ __forceinline__ void mma_bf16(float c[4], const unsigned a[4], const unsigned* b) {
    asm volatile(
        "mma.sync.aligned.m16n8k16.row.col.f32.bf16.bf16.f32 "
        "{%0,%1,%2,%3}, {%4,%5,%6,%7}, {%8,%9}, {%0,%1,%2,%3};"
        : "+f"(c[0]), "+f"(c[1]), "+f"(c[2]), "+f"(c[3])
        : "r"(a[0]), "r"(a[1]), "r"(a[2]), "r"(a[3]), "r"(b[0]), "r"(b[1]));
}
__device__ __forceinline__ void cpasync16(unsigned saddr, const void* gaddr) {
    asm volatile("cp.async.cg.shared.global [%0], [%1], 16;"
                 :: "r"(saddr), "l"(gaddr) : "memory");
}

// ---------------------------------------------------------------
__global__ void k_zero() {
    int i = blockIdx.x * blockDim.x + threadIdx.x;
    if (i < 8) { g_bcnt[i] = 0; g_bgen[i] = 0; }
    if (i < 2 * BB * UU) {
        __nv_bfloat16 z = __float2bfloat16(0.0f);
        g_hh[0][i] = z; g_hl[0][i] = z;
    }
}

// ---------------------------------------------------------------
// One-shot prep: gate-interleave (j = 4u+g) + bf16 hi/lo split of all
// GEMM operands (Wx, Wh, emb); bias interleaved fp32.
// ---------------------------------------------------------------
__global__ void k_prep(const float* __restrict__ WxF, const float* __restrict__ WhF,
                       const float* __restrict__ bF,  const float* __restrict__ WxB,
                       const float* __restrict__ WhB, const float* __restrict__ bB,
                       const float* __restrict__ emb) {
    const int PER = (EE + UU + 1) * G4;
    const int W_TOT = 2 * PER;
    const size_t E_TOT = (size_t)VV * EE;
    size_t tid = (size_t)blockIdx.x * 256 + threadIdx.x;
    if (tid < (size_t)W_TOT) {
        int dir = (int)(tid / PER);
        int r = (int)(tid % PER);
        int row = r / G4, j = r % G4;
        int oc = (j & 3) * UU + (j >> 2);
        float v;
        if (row < EE)            v = (dir ? WxB : WxF)[(size_t)row * G4 + oc];
        else if (row < EE + UU)  v = (dir ? WhB : WhF)[(size_t)(row - EE) * G4 + oc];
        else                     v = (dir ? bB : bF)[oc];
        __nv_bfloat16 h = __float2bfloat16(v);
        __nv_bfloat16 l = __float2bfloat16(v - __bfloat162float(h));
        if (row < EE) {
            size_t o = (size_t)dir * EE * G4 + (size_t)row * G4 + j;
            g_wxh[o] = h; g_wxl[o] = l;
        } else if (row < EE + UU) {
            size_t o = (size_t)dir * UU * G4 + (size_t)(row - EE) * G4 + j;
            g_whh[o] = h; g_whl[o] = l;
        } else {
            g_b[dir * G4 + j] = v;
        }
    } else if (tid < (size_t)W_TOT + E_TOT) {
        size_t i = tid - W_TOT;
        float v = emb[i];
        __nv_bfloat16 h = __float2bfloat16(v);
        g_eh[i] = h;
        g_el[i] = __float2bfloat16(v - __bfloat162float(h));
    }
}

// ---------------------------------------------------------------
// Precompute XW = gather(emb_split, sent) @ Wx_split. Output layout
// (dir, time, b, j). M-tile = 128 batch rows at ONE time step.
// Tile 128x128, KC=16, 256 thr, warps 2m x 4n (warp tile 64x32).
// ---------------------------------------------------------------
__global__ __launch_bounds__(256) void k_pre(const int* __restrict__ sent) {
    const int dir = blockIdx.z;
    const __nv_bfloat16* __restrict__ Bh_g = g_wxh + (size_t)dir * EE * G4;
    const __nv_bfloat16* __restrict__ Bl_g = g_wxl + (size_t)dir * EE * G4;
    const int n0 = blockIdx.x * 128;
    const int time = blockIdx.y % TT;
    const int mb = (blockIdx.y / TT) * 128;

    __shared__ __nv_bfloat16 Ah_s[2][128 * ASTR], Al_s[2][128 * ASTR];
    __shared__ __nv_bfloat16 Bh_s[2][16 * 128], Bl_s[2][16 * 128];
    __shared__ int tok[128];

    const int tid = threadIdx.x;
    const int lane = tid & 31, w = tid >> 5;
    const int wm = w >> 2, wn = w & 3;
    const int gi = lane >> 2, ct = lane & 3;

    if (tid < 128) tok[tid] = sent[(size_t)(mb + tid) * TT + time];
    __syncthreads();

    const int arow = tid >> 1, ahalf = tid & 1;
    const int bk = tid >> 4, bc = tid & 15;
    const size_t tokA = (size_t)tok[arow];
    const int bsw = ((bc * 8) ^ ((bk & 7) << 3));

    const __nv_bfloat16* pa_h = g_eh + tokA * EE + ahalf * 8;
    const __nv_bfloat16* pa_l = g_el + tokA * EE + ahalf * 8;
    const __nv_bfloat16* pb_h = Bh_g + (size_t)bk * G4 + n0 + bc * 8;
    const __nv_bfloat16* pb_l = Bl_g + (size_t)bk * G4 + n0 + bc * 8;

    float acc[4][4][4];
#pragma unroll
    for (int i = 0; i < 4; i++)
#pragma unroll
        for (int j = 0; j < 4; j++)
#pragma unroll
            for (int q = 0; q < 4; q++) acc[i][j][q] = 0.0f;

    {
        uint4 vah = *(const uint4*)pa_h;
        uint4 val = *(const uint4*)pa_l;
        uint4 vbh = *(const uint4*)pb_h;
        uint4 vbl = *(const uint4*)pb_l;
        *(uint4*)&Ah_s[0][arow * ASTR + ahalf * 8] = vah;
        *(uint4*)&Al_s[0][arow * ASTR + ahalf * 8] = val;
        *(uint4*)&Bh_s[0][bk * 128 + bsw] = vbh;
        *(uint4*)&Bl_s[0][bk * 128 + bsw] = vbl;
    }
    __syncthreads();

    const int NK = EE / 16;
    int cur = 0;
    for (int kk = 1; kk <= NK; kk++) {
        uint4 vah, val, vbh, vbl;
        if (kk < NK) {
            vah = *(const uint4*)(pa_h + kk * 16);
            val = *(const uint4*)(pa_l + kk * 16);
            vbh = *(const uint4*)(pb_h + (size_t)kk * 16 * G4);
            vbl = *(const uint4*)(pb_l + (size_t)kk * 16 * G4);
        }
        unsigned afh[4][4], afl[4][4], bfh[2][4], bfl[2][4];
        {
            unsigned abh = sptr(Ah_s[cur]), abl = sptr(Al_s[cur]);
            unsigned aoff = ((wm * 64 + (lane & 15)) * ASTR + (lane >> 4) * 8) * 2;
#pragma unroll
            for (int mt = 0; mt < 4; mt++) {
                ldsm4(afh[mt], abh + aoff + mt * 16 * ASTR * 2);
                ldsm4(afl[mt], abl + aoff + mt * 16 * ASTR * 2);
            }
            unsigned bbh = sptr(Bh_s[cur]), bbl = sptr(Bl_s[cur]);
            int k = lane & 15;
#pragma unroll
            for (int nh = 0; nh < 2; nh++) {
                unsigned nb = (unsigned)((wn * 32 + nh * 16) * 2 + (lane >> 4) * 16);
                unsigned ba = k * 256 + (nb ^ ((k & 7) << 4));
                ldsm4t(bfh[nh], bbh + ba);
                ldsm4t(bfl[nh], bbl + ba);
            }
        }
#pragma unroll
        for (int mt = 0; mt < 4; mt++)
#pragma unroll
            for (int nh = 0; nh < 2; nh++)
#pragma unroll
                for (int sub = 0; sub < 2; sub++) {
                    float* a = acc[mt][nh * 2 + sub];
                    mma_bf16(a, afh[mt], bfh[nh] + sub * 2);
                    mma_bf16(a, afh[mt], bfl[nh] + sub * 2);
                    mma_bf16(a, afl[mt], bfh[nh] + sub * 2);
                }
        if (kk < NK) {
            int nx = cur ^ 1;
            *(uint4*)&Ah_s[nx][arow * ASTR + ahalf * 8] = vah;
            *(uint4*)&Al_s[nx][arow * ASTR + ahalf * 8] = val;
            *(uint4*)&Bh_s[nx][bk * 128 + bsw] = vbh;
            *(uint4*)&Bl_s[nx][bk * 128 + bsw] = vbl;
            __syncthreads();
        }
        cur ^= 1;
    }

    // write (dir, time, b, j)
    float* out = g_xw + ((size_t)(dir * TT + time) * BB) * G4;
#pragma unroll
    for (int mt = 0; mt < 4; mt++) {
#pragma unroll
        for (int nt = 0; nt < 4; nt++) {
            size_t r0 = (size_t)mb + wm * 64 + mt * 16 + gi;
            int cl = n0 + wn * 32 + nt * 8 + 2 * ct;
            *(float2*)(out + r0 * G4 + cl) = make_float2(acc[mt][nt][0], acc[mt][nt][1]);
            *(float2*)(out + (r0 + 8) * G4 + cl) = make_float2(acc[mt][nt][2], acc[mt][nt][3]);
        }
    }
}

// ---------------------------------------------------------------
// Persistent scan: one launch, 256 steps. 128 CTAs = 8 independent
// groups of 16; per-group grid barrier. 512 threads (16 warps, 4m x 4n,
// 32x32 warp tiles) for latency hiding. Wh-hi persistent in smem;
// Wh-lo + h hi/lo streamed; xw prefetched via cp.async; c in registers.
// ---------------------------------------------------------------
__global__ __launch_bounds__(512) void k_scanp() {
    extern __shared__ __align__(16) char smem[];
    __nv_bfloat16* Bh_p = (__nv_bfloat16*)(smem + SM_BH);   // [512][128] swizzled
    __nv_bfloat16* Ah_s = (__nv_bfloat16*)(smem + SM_AH);   // [2][128*ASTR]
    __nv_bfloat16* Al_s = (__nv_bfloat16*)(smem + SM_AL);
    __nv_bfloat16* Bl_s = (__nv_bfloat16*)(smem + SM_BL);   // [2][16*128] swizzled
    float*         xw_s = (float*)(smem + SM_XW);           // [128][128]

    const int tid = threadIdx.x;
    const int lane = tid & 31, w = tid >> 5;
    const int wm = w & 3, wn = w >> 2;      // 4m x 4n warps, 32x32 tiles
    const int gi = lane >> 2, ct = lane & 3;
    const int bid = blockIdx.x;
    const int dir = bid >> 6;
    const int m0 = ((bid >> 4) & 3) * 128;
    const int n0 = (bid & 15) * 128;
    const int grp = bid >> 4;   // 8 groups of 16 CTAs

    // staging roles: tid<256 -> A-hi + Wh-lo; tid>=256 -> A-lo
    const int at = tid & 255;
    const int arow = at >> 1, ahalf = at & 1;
    const int bk = at >> 4, bc = at & 15;
    const int bsw = ((bc * 8) ^ ((bk & 7) << 3));
    const bool loadHi = (tid < 256);

    const __nv_bfloat16* __restrict__ Bh_g = g_whh + (size_t)dir * UU * G4 + n0;
    const __nv_bfloat16* __restrict__ Bl_g = g_whl + (size_t)dir * UU * G4 + n0;
    const float* __restrict__ bias = g_b + dir * G4;

    // persistent Wh-hi preload (swizzled for ldmatrix-trans)
    for (int it = 0; it < 16; it++) {
        int idx = tid + it * 512;
        int row = idx >> 4, c8 = idx & 15;
        uint4 v = *(const uint4*)(Bh_g + (size_t)row * G4 + c8 * 8);
        unsigned eoff = (unsigned)(row * 128 + ((c8 * 8) ^ ((row & 7) << 3)));
        *(uint4*)(Bh_p + eoff) = v;
    }

    float creg[2][4][2];
#pragma unroll
    for (int i = 0; i < 2; i++)
#pragma unroll
        for (int j = 0; j < 4; j++) { creg[i][j][0] = 0.0f; creg[i][j][1] = 0.0f; }

    __syncthreads();

    const size_t hoffA = (size_t)dir * BB * UU + (size_t)(m0 + arow) * UU + ahalf * 8;
    const size_t hb = (size_t)dir * BB * UU;
    const unsigned xw_sb = sptr(xw_s);

    for (int t = 0; t < TT; t++) {
        const int rp = t & 1, wp = rp ^ 1;
        const int time = dir ? (TT - 1 - t) : t;
        // staging source: hi for lower half of threads, lo for upper half
        const __nv_bfloat16* pa = (loadHi ? g_hh[rp] : g_hl[rp]) + hoffA;

        // xw prefetch (coalesced; hidden behind the k-loop)
        {
            const float* xw_src =
                g_xw + ((size_t)(dir * TT + time) * BB + m0) * G4 + n0;
#pragma unroll
            for (int it = 0; it < 8; it++) {
                int idx = tid + it * 512;
                int row = idx >> 5, c4 = (idx & 31) * 4;
                cpasync16(xw_sb + (unsigned)(row * 128 + c4) * 4,
                          xw_src + (size_t)row * G4 + c4);
            }
            asm volatile("cp.async.commit_group;" ::: "memory");
        }

        // stage k-chunk 0
        {
            uint4 va = *(const uint4*)pa;
            if (loadHi) {
                uint4 vbl = *(const uint4*)(Bl_g + (size_t)bk * G4 + bc * 8);
                *(uint4*)&Ah_s[arow * ASTR + ahalf * 8] = va;
                *(uint4*)&Bl_s[bk * 128 + bsw] = vbl;
            } else {
                *(uint4*)&Al_s[arow * ASTR + ahalf * 8] = va;
            }
        }
        __syncthreads();

        float acc[2][4][4];
#pragma unroll
        for (int i = 0; i < 2; i++)
#pragma unroll
            for (int j = 0; j < 4; j++)
#pragma unroll
                for (int q = 0; q < 4; q++) acc[i][j][q] = 0.0f;

        const int NK = UU / 16;  // 32
        int cur = 0;
        for (int kk = 1; kk <= NK; kk++) {
            uint4 va, vbl;
            if (kk < NK) {
                va = *(const uint4*)(pa + kk * 16);
                if (loadHi)
                    vbl = *(const uint4*)(Bl_g + (size_t)(kk * 16 + bk) * G4 + bc * 8);
            }
            unsigned afh[2][4], afl[2][4], bfh[2][4], bfl[2][4];
            {
                unsigned abh = sptr(Ah_s) + cur * (128 * ASTR * 2);
                unsigned abl = sptr(Al_s) + cur * (128 * ASTR * 2);
                unsigned aoff = ((wm * 32 + (lane & 15)) * ASTR + (lane >> 4) * 8) * 2;
#pragma unroll
                for (int mt = 0; mt < 2; mt++) {
                    ldsm4(afh[mt], abh + aoff + mt * 16 * ASTR * 2);
                    ldsm4(afl[mt], abl + aoff + mt * 16 * ASTR * 2);
                }
                int k = lane & 15;
                int kr = (kk - 1) * 16 + k;
                unsigned bbl = sptr(Bl_s) + cur * 4096;
#pragma unroll
                for (int nh = 0; nh < 2; nh++) {
                    unsigned nb = (unsigned)((wn * 32 + nh * 16) * 2 + (lane >> 4) * 16);
                    ldsm4t(bfh[nh], sptr(Bh_p) + kr * 256 + (nb ^ ((kr & 7) << 4)));
                    ldsm4t(bfl[nh], bbl + k * 256 + (nb ^ ((k & 7) << 4)));
                }
            }
#pragma unroll
            for (int mt = 0; mt < 2; mt++)
#pragma unroll
                for (int nh = 0; nh < 2; nh++)
#pragma unroll
                    for (int sub = 0; sub < 2; sub++) {
                        float* a = acc[mt][nh * 2 + sub];
                        mma_bf16(a, afh[mt], bfh[nh] + sub * 2);
                        mma_bf16(a, afh[mt], bfl[nh] + sub * 2);
                        mma_bf16(a, afl[mt], bfh[nh] + sub * 2);
                    }
            if (kk < NK) {
                int nx = cur ^ 1;
                if (loadHi) {
                    *(uint4*)&Ah_s[nx * (128 * ASTR) + arow * ASTR + ahalf * 8] = va;
                    *(uint4*)&Bl_s[nx * 2048 + bk * 128 + bsw] = vbl;
                } else {
                    *(uint4*)&Al_s[nx * (128 * ASTR) + arow * ASTR + ahalf * 8] = va;
                }
                __syncthreads();
            }
            cur ^= 1;
        }

        // make xw tile visible to all threads
        asm volatile("cp.async.wait_group 0;" ::: "memory");
        __syncthreads();

        // epilogue: + xw + bias, shfl-pair (i,f)<->(g,o), LSTM cell (c in regs),
        // write h hi/lo to parity buffer; fp32 h only on last step.
#pragma unroll
        for (int mt = 0; mt < 2; mt++) {
#pragma unroll
            for (int nt = 0; nt < 4; nt++) {
                int lr0 = wm * 32 + mt * 16 + gi;
                int lcl = wn * 32 + nt * 8 + 2 * ct;
                int r0 = m0 + lr0, r1 = r0 + 8;
                int cl = n0 + lcl;
                float2 x0 = *(const float2*)&xw_s[lr0 * 128 + lcl];
                float2 x1 = *(const float2*)&xw_s[(lr0 + 8) * 128 + lcl];
                float2 bb = *(const float2*)(bias + cl);
                float p00 = acc[mt][nt][0] + x0.x + bb.x;
                float p01 = acc[mt][nt][1] + x0.y + bb.y;
                float p10 = acc[mt][nt][2] + x1.x + bb.x;
                float p11 = acc[mt][nt][3] + x1.y + bb.y;
                float q00 = __shfl_xor_sync(0xFFFFFFFFu, p00, 1);
                float q01 = __shfl_xor_sync(0xFFFFFFFFu, p01, 1);
                float q10 = __shfl_xor_sync(0xFFFFFFFFu, p10, 1);
                float q11 = __shfl_xor_sync(0xFFFFFFFFu, p11, 1);
                if ((ct & 1) == 0) {
                    int u = cl >> 2;
                    size_t i0 = hb + (size_t)r0 * UU + u;
                    size_t i1 = hb + (size_t)r1 * UU + u;
                    float c0 = sigf(p01) * creg[mt][nt][0] + sigf(p00) * tanhf(q00);
                    float h0 = sigf(q01) * tanhf(c0);
                    creg[mt][nt][0] = c0;
                    __nv_bfloat16 h0h = __float2bfloat16(h0);
                    g_hh[wp][i0] = h0h;
                    g_hl[wp][i0] = __float2bfloat16(h0 - __bfloat162float(h0h));
                    float c1 = sigf(p11) * creg[mt][nt][1] + sigf(p10) * tanhf(q10);
                    float h1 = sigf(q11) * tanhf(c1);
                    creg[mt][nt][1] = c1;
                    __nv_bfloat16 h1h = __float2bfloat16(h1);
                    g_hh[wp][i1] = h1h;
                    g_hl[wp][i1] = __float2bfloat16(h1 - __bfloat162float(h1h));
                    if (t == TT - 1) { g_h[i0] = h0; g_h[i1] = h1; }
                }
            }
        }

        // per-group barrier (16 CTAs sharing (dir, m-tile)); skip after last step
        if (t + 1 < TT) {
            __threadfence();
            __syncthreads();
            if (tid == 0) {
                unsigned target = (unsigned)(t + 1);
                unsigned old = atomicAdd(&g_bcnt[grp], 1);
                if (old == GRPSZ - 1) {
                    atomicExch(&g_bcnt[grp], 0);
                    __threadfence();
                    atomicExch(&g_bgen[grp], target);
                } else {
                    unsigned g;
                    do {
                        asm volatile("ld.acquire.gpu.u32 %0, [%1];"
                                     : "=r"(g) : "l"(&g_bgen[grp]) : "memory");
                    } while (g < target);
                }
            }
            __syncthreads();
        }
    }
}

// ---------------------------------------------------------------
__global__ void k_hidden(const float* __restrict__ W1, const float* __restrict__ b1) {
    int b = blockIdx.x;
    int j = threadIdx.x;  // 64
    __shared__ float hrow[2 * UU];
    for (int k = j; k < UU; k += HH) {
        hrow[k] = g_h[(size_t)b * UU + k];
        hrow[UU + k] = g_h[(size_t)BB * UU + (size_t)b * UU + k];
    }
    __syncthreads();
    float s = b1[j];
    for (int k = 0; k < 2 * UU; k++) s = fmaf(hrow[k], W1[(size_t)k * HH + j], s);
    g_hidden[b * HH + j] = fmaxf(s, 0.0f);
}

// ---------------------------------------------------------------
__global__ void k_out(const float* __restrict__ W2, const float* __restrict__ b2,
                      float* __restrict__ out) {
    int b = blockIdx.x;
    int tid = threadIdx.x;
    __shared__ float hid[HH];
    __shared__ float red[256];
    if (tid < HH) hid[tid] = g_hidden[b * HH + tid];
    __syncthreads();

    float lmax = -3.0e38f;
    for (int v = tid; v < VV; v += 256) {
        float s = b2[v];
#pragma unroll
        for (int k = 0; k < HH; k++) s = fmaf(hid[k], W2[(size_t)k * VV + v], s);
        out[(size_t)b * VV + v] = s;
        lmax = fmaxf(lmax, s);
    }
    red[tid] = lmax;
    __syncthreads();
    for (int s = 128; s > 0; s >>= 1) {
        if (tid < s) red[tid] = fmaxf(red[tid], red[tid + s]);
        __syncthreads();
    }
    float mx = red[0];
    __syncthreads();

    float lsum = 0.0f;
    for (int v = tid; v < VV; v += 256) {
        float e = expf(out[(size_t)b * VV + v] - mx);
        out[(size_t)b * VV + v] = e;
        lsum += e;
    }
    red[tid] = lsum;
    __syncthreads();
    for (int s = 128; s > 0; s >>= 1) {
        if (tid < s) red[tid] += red[tid + s];
        __syncthreads();
    }
    float inv = 1.0f / red[0];
    __syncthreads();

    for (int v = tid; v < VV; v += 256) out[(size_t)b * VV + v] *= inv;
}

// ---------------------------------------------------------------
extern "C" void kernel_launch(void* const* d_in, const int* in_sizes, int n_in,
                              void* d_out, int out_size) {
    const int*   sent = (const int*)d_in[0];
    const float* emb  = (const float*)d_in[1];
    const float* WxF  = (const float*)d_in[2];
    const float* WhF  = (const float*)d_in[3];
    const float* bF   = (const float*)d_in[4];
    const float* WxB  = (const float*)d_in[5];
    const float* WhB  = (const float*)d_in[6];
    const float* bB   = (const float*)d_in[7];
    const float* W1   = (const float*)d_in[8];
    const float* b1   = (const float*)d_in[9];
    const float* W2   = (const float*)d_in[10];
    const float* b2   = (const float*)d_in[11];
    float* out = (float*)d_out;

    cudaFuncSetAttribute(k_scanp, cudaFuncAttributeMaxDynamicSharedMemorySize, SMEM_TOT);

    k_zero<<<(2 * BB * UU + 255) / 256, 256>>>();

    const size_t prep_total = (size_t)2 * (EE + UU + 1) * G4 + (size_t)VV * EE;
    k_prep<<<(int)((prep_total + 255) / 256), 256>>>(WxF, WhF, bF, WxB, WhB, bB, emb);

    dim3 gp(G4 / 128, (BB / 128) * TT, 2);  // (16, 1024, 2)
    k_pre<<<gp, 256>>>(sent);

    k_scanp<<<NCTA, 512, SMEM_TOT>>>();

    k_hidden<<<BB, HH>>>(W1, b1);
    k_out<<<BB, 256>>>(W2, b2, out);
}